// round 15
// baseline (speedup 1.0000x reference)
#include <cuda_runtime.h>
#include <math.h>

#define CCH 62
#define TT  2000
#define NB  256
#define TIL 128
#define NTILE ((TT + TIL - 1) / TIL)   // 16

// ---------------------------------------------------------------------------
// Fused kernel: covariance (smem) -> A = W Cov W^T + eps I -> two-sided
// parallel Jacobi (ping-pong A, 1 barrier/round, warp-uniform inactivity
// guards) -> log-map GEMM -> triu -> proj+relu -> head. One CTA per batch.
// ---------------------------------------------------------------------------
__global__ __launch_bounds__(256, 2) void fused_kernel(
    const float* __restrict__ x,
    const float* __restrict__ conv_w,
    const float* __restrict__ proj_w, const float* __restrict__ proj_b,
    const float* __restrict__ head_w, const float* __restrict__ head_b,
    float* __restrict__ out)
{
    __shared__ __align__(16) float S[16324];
    float* Abuf0 = S;
    float* Abuf1 = S + 4160;
    float* Vsm   = S + 8320;
    float* Wbuf  = S + 12416;
    float* ssum  = S + 16260;
    float* xs    = S;                 // cov-phase alias of Abuf0+Abuf1

    float* vec  = Wbuf;               // [1953] (Wbuf dead when live)
    float* logl = Wbuf + 2048;        // [64]
    float* feat = Wbuf + 2112;        // [64]

    const int b    = blockIdx.x;
    const int tid  = threadIdx.x;
    const int wid  = tid >> 5;
    const int lane = tid & 31;
    const int ti   = tid >> 4;
    const int tj   = tid & 15;

    // ================= cov phase =================
    int bi = 0, bj = 0;
    const bool act = (tid < 136);
    if (act) {
        int z = tid;
        while (z >= 16 - bi) { z -= 16 - bi; bi++; }
        bj = bi + z;
    }

    {
        float acc[16];
#pragma unroll
        for (int r = 0; r < 16; r++) acc[r] = 0.f;
        float mysum = 0.f;

        const float* xb = x + (size_t)b * CCH * TT;

        for (int tile = 0; tile < NTILE; tile++) {
            const int t0 = tile * TIL;
#pragma unroll
            for (int k = 0; k < 16; k++) {
                const int f = tid + (k << 8);
                const int c = f >> 6;
                const int u = f & 63;
                const int t = t0 + u * 2;
                float2 v = make_float2(0.f, 0.f);
                if (c < CCH && t < TT) v = *(const float2*)(xb + c * TT + t);
                *(float2*)(xs + c * 130 + u * 2) = v;
            }
            __syncthreads();

            if (tid < CCH) {
                const float2* rp = (const float2*)(xs + tid * 130);
#pragma unroll 8
                for (int tl = 0; tl < 64; tl++) {
                    const float2 v = rp[tl];
                    mysum += v.x + v.y;
                }
            }

            if (act) {
                const float2* r0 = (const float2*)(xs + (4 * bi + 0) * 130);
                const float2* r1 = (const float2*)(xs + (4 * bi + 1) * 130);
                const float2* r2 = (const float2*)(xs + (4 * bi + 2) * 130);
                const float2* r3 = (const float2*)(xs + (4 * bi + 3) * 130);
                const float2* c0 = (const float2*)(xs + (4 * bj + 0) * 130);
                const float2* c1 = (const float2*)(xs + (4 * bj + 1) * 130);
                const float2* c2 = (const float2*)(xs + (4 * bj + 2) * 130);
                const float2* c3 = (const float2*)(xs + (4 * bj + 3) * 130);

#pragma unroll 4
                for (int tl = 0; tl < 64; tl++) {
                    const float2 a0 = r0[tl], a1 = r1[tl], a2 = r2[tl], a3 = r3[tl];
                    const float2 b0 = c0[tl], b1 = c1[tl], b2 = c2[tl], b3 = c3[tl];
                    acc[0]  += a0.x * b0.x + a0.y * b0.y;
                    acc[1]  += a0.x * b1.x + a0.y * b1.y;
                    acc[2]  += a0.x * b2.x + a0.y * b2.y;
                    acc[3]  += a0.x * b3.x + a0.y * b3.y;
                    acc[4]  += a1.x * b0.x + a1.y * b0.y;
                    acc[5]  += a1.x * b1.x + a1.y * b1.y;
                    acc[6]  += a1.x * b2.x + a1.y * b2.y;
                    acc[7]  += a1.x * b3.x + a1.y * b3.y;
                    acc[8]  += a2.x * b0.x + a2.y * b0.y;
                    acc[9]  += a2.x * b1.x + a2.y * b1.y;
                    acc[10] += a2.x * b2.x + a2.y * b2.y;
                    acc[11] += a2.x * b3.x + a2.y * b3.y;
                    acc[12] += a3.x * b0.x + a3.y * b0.y;
                    acc[13] += a3.x * b1.x + a3.y * b1.y;
                    acc[14] += a3.x * b2.x + a3.y * b2.y;
                    acc[15] += a3.x * b3.x + a3.y * b3.y;
                }
            }
            __syncthreads();
        }

        if (tid < 64) ssum[tid] = (tid < CCH) ? mysum : 0.f;
        __syncthreads();          // xs dead from here; Abuf0 writes safe

        if (act) {
#pragma unroll
            for (int r = 0; r < 4; r++) {
#pragma unroll
                for (int u = 0; u < 4; u++) {
                    const int i = 4 * bi + r;
                    const int j = 4 * bj + u;
                    const float v = (acc[r * 4 + u] -
                                     ssum[i] * ssum[j] * (1.f / 2000.f)) * (1.f / 1999.f);
                    Abuf0[i * 65 + j] = v;
                    Abuf0[j * 65 + i] = v;
                }
            }
        }
    }
    for (int idx = tid; idx < 62 * 62; idx += 256) Wbuf[idx] = conv_w[idx];
    __syncthreads();

    // ================= conjugation: A = W Cov W^T =================
    {
        float acc[16];
#pragma unroll
        for (int r = 0; r < 16; r++) acc[r] = 0.f;
        for (int k = 0; k < 62; k++) {
            float wv[4], cv[4];
#pragma unroll
            for (int r = 0; r < 4; r++) {
                const int i = 4 * ti + r;
                wv[r] = (i < 62) ? Wbuf[i * 62 + k] : 0.f;
            }
#pragma unroll
            for (int u = 0; u < 4; u++) cv[u] = Abuf0[k * 65 + 4 * tj + u];
#pragma unroll
            for (int r = 0; r < 4; r++)
#pragma unroll
                for (int u = 0; u < 4; u++) acc[r * 4 + u] += wv[r] * cv[u];
        }
#pragma unroll
        for (int r = 0; r < 4; r++)
#pragma unroll
            for (int u = 0; u < 4; u++)
                Vsm[(4 * ti + r) * 64 + 4 * tj + u] = acc[r * 4 + u];
    }
    __syncthreads();

    {
        float acc[16];
#pragma unroll
        for (int r = 0; r < 16; r++) acc[r] = 0.f;
        for (int k = 0; k < 62; k++) {
            float mv[4], wv[4];
#pragma unroll
            for (int r = 0; r < 4; r++) mv[r] = Vsm[(4 * ti + r) * 64 + k];
#pragma unroll
            for (int u = 0; u < 4; u++) {
                const int j = 4 * tj + u;
                wv[u] = (j < 62) ? Wbuf[j * 62 + k] : 0.f;
            }
#pragma unroll
            for (int r = 0; r < 4; r++)
#pragma unroll
                for (int u = 0; u < 4; u++) acc[r * 4 + u] += mv[r] * wv[u];
        }
#pragma unroll
        for (int r = 0; r < 4; r++)
#pragma unroll
            for (int u = 0; u < 4; u++)
                Abuf0[(4 * ti + r) * 65 + 4 * tj + u] = acc[r * 4 + u];
    }
    __syncthreads();

    // ---- symmetrize + SPD eps + pad diag ----
    {
        float v[16];
#pragma unroll
        for (int r = 0; r < 4; r++)
#pragma unroll
            for (int u = 0; u < 4; u++) {
                const int i = 4 * ti + r, j = 4 * tj + u;
                v[r * 4 + u] = 0.5f * (Abuf0[i * 65 + j] + Abuf0[j * 65 + i]);
            }
        __syncthreads();
#pragma unroll
        for (int r = 0; r < 4; r++)
#pragma unroll
            for (int u = 0; u < 4; u++) {
                const int i = 4 * ti + r, j = 4 * tj + u;
                float val = v[r * 4 + u];
                if (i == j) val = (i < 62) ? val + 1e-3f : 1.0f;
                Abuf0[i * 65 + j] = val;
            }
    }
    for (int idx = tid; idx < 4096; idx += 256)
        Vsm[idx] = ((idx >> 6) == (idx & 63)) ? 1.f : 0.f;
    __syncthreads();

    // ================= two-sided parallel Jacobi =================
    int pReg = (lane == 0) ? 63 : lane;
    int qReg = (lane == 0) ? 0  : 63 - lane;
    int prowR[4], qrowR[4];
#pragma unroll
    for (int it = 0; it < 4; it++) {
        const int kk = 8 * it + wid;
        prowR[it] = (kk == 0) ? 63 : kk;
        qrowR[it] = (kk == 0) ? 0  : 63 - kk;
    }
    const bool kk0 = (wid == 0);

    float* Acur = Abuf0;
    float* Anxt = Abuf1;
    for (int sweep = 0; sweep < 9; sweep++) {
        bool any_sweep_rot = false;
        for (int r = 0; r < 63; r++) {
            const int p = pReg, q = qReg;
            int prow[4], qrow[4];
#pragma unroll
            for (int it = 0; it < 4; it++) { prow[it] = prowR[it]; qrow[it] = qrowR[it]; }

            // advance tournament registers (even on skipped rounds)
            if (lane) { pReg++; if (pReg == 63) pReg = 0; }
            qReg++; if (qReg == 63) qReg = 0;
#pragma unroll
            for (int it = 0; it < 4; it++) {
                if (!(it == 0 && kk0)) { prowR[it]++; if (prowR[it] == 63) prowR[it] = 0; }
                qrowR[it]++; if (qrowR[it] == 63) qrowR[it] = 0;
            }

            const float app = Acur[p * 65 + p];
            const float aqq = Acur[q * 65 + q];
            const float apq = Acur[p * 65 + q];
            float cO = 1.f, sO = 0.f;
            if (apq * apq > 3e-8f * app * aqq) {    // relative skip
                const float tau = (aqq - app) / (2.f * apq);
                const float t2  = ((tau >= 0.f) ? 1.f : -1.f) /
                                  (fabsf(tau) + sqrtf(1.f + tau * tau));
                cO = rsqrtf(1.f + t2 * t2);
                sO = t2 * cO;
            }
            const unsigned rotmask = __ballot_sync(0xffffffffu, sO != 0.f);
            if (rotmask == 0u) continue;   // fully skipped round
            any_sweep_rot = true;

            // A loads: addresses ready at round entry, batch for MLP
            float a00[4], a01[4], a10[4], a11[4];
#pragma unroll
            for (int it = 0; it < 4; it++) {
                const int rp = prow[it] * 65, rq = qrow[it] * 65;
                a00[it] = Acur[rp + p]; a01[it] = Acur[rp + q];
                a10[it] = Acur[rq + p]; a11[it] = Acur[rq + q];
            }
            float cr[4], sr[4];
#pragma unroll
            for (int it = 0; it < 4; it++) {
                const int kk = 8 * it + wid;                       // warp-uniform
                cr[it] = __shfl_sync(0xffffffffu, cO, kk);
                sr[it] = __shfl_sync(0xffffffffu, sO, kk);
            }

            // A update: full two-sided when row pair active, column-only else
#pragma unroll
            for (int it = 0; it < 4; it++) {
                const int rp = prow[it] * 65, rq = qrow[it] * 65;
                if (sr[it] != 0.f) {                               // uniform branch
                    const float b00 = cr[it] * a00[it] - sr[it] * a10[it];
                    const float b01 = cr[it] * a01[it] - sr[it] * a11[it];
                    const float b10 = sr[it] * a00[it] + cr[it] * a10[it];
                    const float b11 = sr[it] * a01[it] + cr[it] * a11[it];
                    Anxt[rp + p] = cO * b00 - sO * b01;
                    Anxt[rp + q] = sO * b00 + cO * b01;
                    Anxt[rq + p] = cO * b10 - sO * b11;
                    Anxt[rq + q] = sO * b10 + cO * b11;
                } else {                                           // column-only
                    Anxt[rp + p] = cO * a00[it] - sO * a01[it];
                    Anxt[rp + q] = sO * a00[it] + cO * a01[it];
                    Anxt[rq + p] = cO * a10[it] - sO * a11[it];
                    Anxt[rq + q] = sO * a10[it] + cO * a11[it];
                }
            }

            // V update: rows untouched when sr == 0 (in-place, skip entirely)
#pragma unroll
            for (int it = 0; it < 4; it++) {
                if (sr[it] != 0.f) {                               // uniform branch
                    float2* vp = (float2*)(Vsm + (prow[it] << 6)) + lane;
                    float2* vq = (float2*)(Vsm + (qrow[it] << 6)) + lane;
                    const float2 xp = *vp, xq = *vq;
                    float2 np, nq;
                    np.x = cr[it] * xp.x - sr[it] * xq.x;
                    np.y = cr[it] * xp.y - sr[it] * xq.y;
                    nq.x = sr[it] * xp.x + cr[it] * xq.x;
                    nq.y = sr[it] * xp.y + cr[it] * xq.y;
                    *vp = np; *vq = nq;
                }
            }
            // flip; single barrier orders writes vs next round's reads
            float* t = Acur; Acur = Anxt; Anxt = t;
            __syncthreads();
        }

        if (!any_sweep_rot) break;
    }

    // ================= log-map + epilogue =================
    if (tid < 64) {
        const float d = Acur[tid * 65 + tid];
        logl[tid] = logf(fmaxf(d, 1e-6f));
    }
    __syncthreads();
    for (int idx = tid; idx < 4096; idx += 256) {
        const int k = idx >> 6, i = idx & 63;
        Acur[k * 65 + i] = logl[k] * Vsm[idx];
    }
    __syncthreads();

    // log_cov = B^T Q via 4x4 block GEMM, triu straight to vec
    {
        float acc[16];
#pragma unroll
        for (int r = 0; r < 16; r++) acc[r] = 0.f;
        for (int k = 0; k < 64; k++) {
            float bb[4];
#pragma unroll
            for (int r = 0; r < 4; r++) bb[r] = Acur[k * 65 + 4 * ti + r];
            const float4 qv = *((const float4*)(Vsm + k * 64) + tj);
#pragma unroll
            for (int r = 0; r < 4; r++) {
                acc[r * 4 + 0] += bb[r] * qv.x;
                acc[r * 4 + 1] += bb[r] * qv.y;
                acc[r * 4 + 2] += bb[r] * qv.z;
                acc[r * 4 + 3] += bb[r] * qv.w;
            }
        }
        __syncthreads();   // Acur/Vsm reads done before vec (Wbuf) written
#pragma unroll
        for (int r = 0; r < 4; r++) {
#pragma unroll
            for (int u = 0; u < 4; u++) {
                const int i = 4 * ti + r, j = 4 * tj + u;
                if (i <= j && j < 62)
                    vec[i * (125 - i) / 2 + (j - i)] = acc[r * 4 + u];
            }
        }
    }
    __syncthreads();

    // MLP: feat = relu(vec @ proj^T + b), 8 outputs per warp
    {
#pragma unroll
        for (int hh = 0; hh < 8; hh++) {
            const int h = (wid << 3) + hh;
            const float* pw = proj_w + h * 1953;
            float acc = 0.f;
            for (int i = lane; i < 1953; i += 32) acc += vec[i] * pw[i];
#pragma unroll
            for (int off = 16; off; off >>= 1)
                acc += __shfl_down_sync(0xffffffffu, acc, off);
            if (lane == 0) feat[h] = fmaxf(acc + proj_b[h], 0.f);
        }
    }
    __syncthreads();

    // head: 3 logits
    if (tid < 3) {
        float acc = head_b[tid];
        const float* hw = head_w + tid * 64;
#pragma unroll
        for (int h = 0; h < 64; h++) acc += feat[h] * hw[h];
        out[b * 3 + tid] = acc;
    }
}

// ---------------------------------------------------------------------------
extern "C" void kernel_launch(void* const* d_in, const int* in_sizes, int n_in,
                              void* d_out, int out_size)
{
    const float* x      = (const float*)d_in[0];
    const float* conv_w = (const float*)d_in[1];
    // d_in[2] = conv_b: cancels exactly under mean-centering; unused.
    const float* proj_w = (const float*)d_in[3];
    const float* proj_b = (const float*)d_in[4];
    const float* head_w = (const float*)d_in[5];
    const float* head_b = (const float*)d_in[6];

    int B = in_sizes[0] / (CCH * TT);
    if (B > NB) B = NB;

    fused_kernel<<<B, 256>>>(x, conv_w, proj_w, proj_b, head_w, head_b,
                             (float*)d_out);
}

// round 16
// speedup vs baseline: 1.0464x; 1.0464x over previous
#include <cuda_runtime.h>
#include <math.h>

#define CCH 62
#define TT  2000
#define NB  256
#define TIL 128
#define NTILE ((TT + TIL - 1) / TIL)   // 16

// ---------------------------------------------------------------------------
// Fused kernel (R13 structure, branch-free dense rounds, skip thr 3e-8):
// covariance (smem) -> A = W Cov W^T + eps I -> two-sided parallel Jacobi
// (ping-pong A, 1 barrier/round, incremental tournament registers) ->
// log-map GEMM -> triu -> proj+relu -> head.  One CTA (256 thr) per batch.
// ---------------------------------------------------------------------------
__global__ __launch_bounds__(256, 2) void fused_kernel(
    const float* __restrict__ x,
    const float* __restrict__ conv_w,
    const float* __restrict__ proj_w, const float* __restrict__ proj_b,
    const float* __restrict__ head_w, const float* __restrict__ head_b,
    float* __restrict__ out)
{
    __shared__ __align__(16) float S[16324];
    float* Abuf0 = S;
    float* Abuf1 = S + 4160;
    float* Vsm   = S + 8320;
    float* Wbuf  = S + 12416;
    float* ssum  = S + 16260;
    float* xs    = S;                 // cov-phase alias of Abuf0+Abuf1

    float* vec  = Wbuf;               // [1953] (Wbuf dead when live)
    float* logl = Wbuf + 2048;        // [64]
    float* feat = Wbuf + 2112;        // [64]

    const int b    = blockIdx.x;
    const int tid  = threadIdx.x;
    const int wid  = tid >> 5;
    const int lane = tid & 31;
    const int ti   = tid >> 4;
    const int tj   = tid & 15;

    // ================= cov phase =================
    int bi = 0, bj = 0;
    const bool act = (tid < 136);
    if (act) {
        int z = tid;
        while (z >= 16 - bi) { z -= 16 - bi; bi++; }
        bj = bi + z;
    }

    {
        float acc[16];
#pragma unroll
        for (int r = 0; r < 16; r++) acc[r] = 0.f;
        float mysum = 0.f;

        const float* xb = x + (size_t)b * CCH * TT;

        for (int tile = 0; tile < NTILE; tile++) {
            const int t0 = tile * TIL;
#pragma unroll
            for (int k = 0; k < 16; k++) {
                const int f = tid + (k << 8);
                const int c = f >> 6;
                const int u = f & 63;
                const int t = t0 + u * 2;
                float2 v = make_float2(0.f, 0.f);
                if (c < CCH && t < TT) v = *(const float2*)(xb + c * TT + t);
                *(float2*)(xs + c * 130 + u * 2) = v;
            }
            __syncthreads();

            if (tid < CCH) {
                const float2* rp = (const float2*)(xs + tid * 130);
#pragma unroll 8
                for (int tl = 0; tl < 64; tl++) {
                    const float2 v = rp[tl];
                    mysum += v.x + v.y;
                }
            }

            if (act) {
                const float2* r0 = (const float2*)(xs + (4 * bi + 0) * 130);
                const float2* r1 = (const float2*)(xs + (4 * bi + 1) * 130);
                const float2* r2 = (const float2*)(xs + (4 * bi + 2) * 130);
                const float2* r3 = (const float2*)(xs + (4 * bi + 3) * 130);
                const float2* c0 = (const float2*)(xs + (4 * bj + 0) * 130);
                const float2* c1 = (const float2*)(xs + (4 * bj + 1) * 130);
                const float2* c2 = (const float2*)(xs + (4 * bj + 2) * 130);
                const float2* c3 = (const float2*)(xs + (4 * bj + 3) * 130);

#pragma unroll 4
                for (int tl = 0; tl < 64; tl++) {
                    const float2 a0 = r0[tl], a1 = r1[tl], a2 = r2[tl], a3 = r3[tl];
                    const float2 b0 = c0[tl], b1 = c1[tl], b2 = c2[tl], b3 = c3[tl];
                    acc[0]  += a0.x * b0.x + a0.y * b0.y;
                    acc[1]  += a0.x * b1.x + a0.y * b1.y;
                    acc[2]  += a0.x * b2.x + a0.y * b2.y;
                    acc[3]  += a0.x * b3.x + a0.y * b3.y;
                    acc[4]  += a1.x * b0.x + a1.y * b0.y;
                    acc[5]  += a1.x * b1.x + a1.y * b1.y;
                    acc[6]  += a1.x * b2.x + a1.y * b2.y;
                    acc[7]  += a1.x * b3.x + a1.y * b3.y;
                    acc[8]  += a2.x * b0.x + a2.y * b0.y;
                    acc[9]  += a2.x * b1.x + a2.y * b1.y;
                    acc[10] += a2.x * b2.x + a2.y * b2.y;
                    acc[11] += a2.x * b3.x + a2.y * b3.y;
                    acc[12] += a3.x * b0.x + a3.y * b0.y;
                    acc[13] += a3.x * b1.x + a3.y * b1.y;
                    acc[14] += a3.x * b2.x + a3.y * b2.y;
                    acc[15] += a3.x * b3.x + a3.y * b3.y;
                }
            }
            __syncthreads();
        }

        if (tid < 64) ssum[tid] = (tid < CCH) ? mysum : 0.f;
        __syncthreads();          // xs dead from here; Abuf0 writes safe

        if (act) {
#pragma unroll
            for (int r = 0; r < 4; r++) {
#pragma unroll
                for (int u = 0; u < 4; u++) {
                    const int i = 4 * bi + r;
                    const int j = 4 * bj + u;
                    const float v = (acc[r * 4 + u] -
                                     ssum[i] * ssum[j] * (1.f / 2000.f)) * (1.f / 1999.f);
                    Abuf0[i * 65 + j] = v;
                    Abuf0[j * 65 + i] = v;
                }
            }
        }
    }
    for (int idx = tid; idx < 62 * 62; idx += 256) Wbuf[idx] = conv_w[idx];
    __syncthreads();

    // ================= conjugation: A = W Cov W^T =================
    {
        float acc[16];
#pragma unroll
        for (int r = 0; r < 16; r++) acc[r] = 0.f;
        for (int k = 0; k < 62; k++) {
            float wv[4], cv[4];
#pragma unroll
            for (int r = 0; r < 4; r++) {
                const int i = 4 * ti + r;
                wv[r] = (i < 62) ? Wbuf[i * 62 + k] : 0.f;
            }
#pragma unroll
            for (int u = 0; u < 4; u++) cv[u] = Abuf0[k * 65 + 4 * tj + u];
#pragma unroll
            for (int r = 0; r < 4; r++)
#pragma unroll
                for (int u = 0; u < 4; u++) acc[r * 4 + u] += wv[r] * cv[u];
        }
#pragma unroll
        for (int r = 0; r < 4; r++)
#pragma unroll
            for (int u = 0; u < 4; u++)
                Vsm[(4 * ti + r) * 64 + 4 * tj + u] = acc[r * 4 + u];
    }
    __syncthreads();

    {
        float acc[16];
#pragma unroll
        for (int r = 0; r < 16; r++) acc[r] = 0.f;
        for (int k = 0; k < 62; k++) {
            float mv[4], wv[4];
#pragma unroll
            for (int r = 0; r < 4; r++) mv[r] = Vsm[(4 * ti + r) * 64 + k];
#pragma unroll
            for (int u = 0; u < 4; u++) {
                const int j = 4 * tj + u;
                wv[u] = (j < 62) ? Wbuf[j * 62 + k] : 0.f;
            }
#pragma unroll
            for (int r = 0; r < 4; r++)
#pragma unroll
                for (int u = 0; u < 4; u++) acc[r * 4 + u] += mv[r] * wv[u];
        }
#pragma unroll
        for (int r = 0; r < 4; r++)
#pragma unroll
            for (int u = 0; u < 4; u++)
                Abuf0[(4 * ti + r) * 65 + 4 * tj + u] = acc[r * 4 + u];
    }
    __syncthreads();

    // ---- symmetrize + SPD eps + pad diag ----
    {
        float v[16];
#pragma unroll
        for (int r = 0; r < 4; r++)
#pragma unroll
            for (int u = 0; u < 4; u++) {
                const int i = 4 * ti + r, j = 4 * tj + u;
                v[r * 4 + u] = 0.5f * (Abuf0[i * 65 + j] + Abuf0[j * 65 + i]);
            }
        __syncthreads();
#pragma unroll
        for (int r = 0; r < 4; r++)
#pragma unroll
            for (int u = 0; u < 4; u++) {
                const int i = 4 * ti + r, j = 4 * tj + u;
                float val = v[r * 4 + u];
                if (i == j) val = (i < 62) ? val + 1e-3f : 1.0f;
                Abuf0[i * 65 + j] = val;
            }
    }
    for (int idx = tid; idx < 4096; idx += 256)
        Vsm[idx] = ((idx >> 6) == (idx & 63)) ? 1.f : 0.f;
    __syncthreads();

    // ================= two-sided parallel Jacobi =================
    int pReg = (lane == 0) ? 63 : lane;
    int qReg = (lane == 0) ? 0  : 63 - lane;
    int prowR[4], qrowR[4];
#pragma unroll
    for (int it = 0; it < 4; it++) {
        const int kk = 8 * it + wid;
        prowR[it] = (kk == 0) ? 63 : kk;
        qrowR[it] = (kk == 0) ? 0  : 63 - kk;
    }
    const bool kk0 = (wid == 0);

    float* Acur = Abuf0;
    float* Anxt = Abuf1;
    for (int sweep = 0; sweep < 9; sweep++) {
        bool any_sweep_rot = false;
        for (int r = 0; r < 63; r++) {
            const int p = pReg, q = qReg;
            int prow[4], qrow[4];
#pragma unroll
            for (int it = 0; it < 4; it++) { prow[it] = prowR[it]; qrow[it] = qrowR[it]; }

            // advance tournament registers (even on skipped rounds)
            if (lane) { pReg++; if (pReg == 63) pReg = 0; }
            qReg++; if (qReg == 63) qReg = 0;
#pragma unroll
            for (int it = 0; it < 4; it++) {
                if (!(it == 0 && kk0)) { prowR[it]++; if (prowR[it] == 63) prowR[it] = 0; }
                qrowR[it]++; if (qrowR[it] == 63) qrowR[it] = 0;
            }

            const float app = Acur[p * 65 + p];
            const float aqq = Acur[q * 65 + q];
            const float apq = Acur[p * 65 + q];
            float cO = 1.f, sO = 0.f;
            if (apq * apq > 3e-8f * app * aqq) {    // relative skip
                const float tau = (aqq - app) / (2.f * apq);
                const float t2  = ((tau >= 0.f) ? 1.f : -1.f) /
                                  (fabsf(tau) + sqrtf(1.f + tau * tau));
                cO = rsqrtf(1.f + t2 * t2);
                sO = t2 * cO;
            }
            const unsigned rotmask = __ballot_sync(0xffffffffu, sO != 0.f);
            if (rotmask == 0u) continue;   // skipped round: no writes, no flip
            any_sweep_rot = true;

            // loads: addresses ready at round entry -> batch immediately,
            // overlapping the cr/sr shfls below (branch-free, MLP ~8)
            float a00[4], a01[4], a10[4], a11[4];
            float2 xp[4], xq[4];
#pragma unroll
            for (int it = 0; it < 4; it++) {
                const int rp = prow[it] * 65, rq = qrow[it] * 65;
                a00[it] = Acur[rp + p]; a01[it] = Acur[rp + q];
                a10[it] = Acur[rq + p]; a11[it] = Acur[rq + q];
            }
#pragma unroll
            for (int it = 0; it < 4; it++) {
                xp[it] = *((float2*)(Vsm + (prow[it] << 6)) + lane);
                xq[it] = *((float2*)(Vsm + (qrow[it] << 6)) + lane);
            }
            float cr[4], sr[4];
#pragma unroll
            for (int it = 0; it < 4; it++) {
                const int kk = 8 * it + wid;                       // warp-uniform
                cr[it] = __shfl_sync(0xffffffffu, cO, kk);
                sr[it] = __shfl_sync(0xffffffffu, sO, kk);
            }
#pragma unroll
            for (int it = 0; it < 4; it++) {
                const int rp = prow[it] * 65, rq = qrow[it] * 65;
                const float b00 = cr[it] * a00[it] - sr[it] * a10[it];
                const float b01 = cr[it] * a01[it] - sr[it] * a11[it];
                const float b10 = sr[it] * a00[it] + cr[it] * a10[it];
                const float b11 = sr[it] * a01[it] + cr[it] * a11[it];
                Anxt[rp + p] = cO * b00 - sO * b01;
                Anxt[rp + q] = sO * b00 + cO * b01;
                Anxt[rq + p] = cO * b10 - sO * b11;
                Anxt[rq + q] = sO * b10 + cO * b11;
            }
#pragma unroll
            for (int it = 0; it < 4; it++) {
                float2 np, nq;
                np.x = cr[it] * xp[it].x - sr[it] * xq[it].x;
                np.y = cr[it] * xp[it].y - sr[it] * xq[it].y;
                nq.x = sr[it] * xp[it].x + cr[it] * xq[it].x;
                nq.y = sr[it] * xp[it].y + cr[it] * xq[it].y;
                *((float2*)(Vsm + (prow[it] << 6)) + lane) = np;
                *((float2*)(Vsm + (qrow[it] << 6)) + lane) = nq;
            }
            // flip; single barrier orders writes vs next round's reads
            float* t = Acur; Acur = Anxt; Anxt = t;
            __syncthreads();
        }

        if (!any_sweep_rot) break;
    }

    // ================= log-map + epilogue =================
    if (tid < 64) {
        const float d = Acur[tid * 65 + tid];
        logl[tid] = logf(fmaxf(d, 1e-6f));
    }
    __syncthreads();
    for (int idx = tid; idx < 4096; idx += 256) {
        const int k = idx >> 6, i = idx & 63;
        Acur[k * 65 + i] = logl[k] * Vsm[idx];
    }
    __syncthreads();

    // log_cov = B^T Q via 4x4 block GEMM, triu straight to vec
    {
        float acc[16];
#pragma unroll
        for (int r = 0; r < 16; r++) acc[r] = 0.f;
        for (int k = 0; k < 64; k++) {
            float bb[4];
#pragma unroll
            for (int r = 0; r < 4; r++) bb[r] = Acur[k * 65 + 4 * ti + r];
            const float4 qv = *((const float4*)(Vsm + k * 64) + tj);
#pragma unroll
            for (int r = 0; r < 4; r++) {
                acc[r * 4 + 0] += bb[r] * qv.x;
                acc[r * 4 + 1] += bb[r] * qv.y;
                acc[r * 4 + 2] += bb[r] * qv.z;
                acc[r * 4 + 3] += bb[r] * qv.w;
            }
        }
        __syncthreads();   // Acur/Vsm reads done before vec (Wbuf) written
#pragma unroll
        for (int r = 0; r < 4; r++) {
#pragma unroll
            for (int u = 0; u < 4; u++) {
                const int i = 4 * ti + r, j = 4 * tj + u;
                if (i <= j && j < 62)
                    vec[i * (125 - i) / 2 + (j - i)] = acc[r * 4 + u];
            }
        }
    }
    __syncthreads();

    // MLP: feat = relu(vec @ proj^T + b), 8 outputs per warp
    {
#pragma unroll
        for (int hh = 0; hh < 8; hh++) {
            const int h = (wid << 3) + hh;
            const float* pw = proj_w + h * 1953;
            float acc = 0.f;
            for (int i = lane; i < 1953; i += 32) acc += vec[i] * pw[i];
#pragma unroll
            for (int off = 16; off; off >>= 1)
                acc += __shfl_down_sync(0xffffffffu, acc, off);
            if (lane == 0) feat[h] = fmaxf(acc + proj_b[h], 0.f);
        }
    }
    __syncthreads();

    // head: 3 logits
    if (tid < 3) {
        float acc = head_b[tid];
        const float* hw = head_w + tid * 64;
#pragma unroll
        for (int h = 0; h < 64; h++) acc += feat[h] * hw[h];
        out[b * 3 + tid] = acc;
    }
}

// ---------------------------------------------------------------------------
extern "C" void kernel_launch(void* const* d_in, const int* in_sizes, int n_in,
                              void* d_out, int out_size)
{
    const float* x      = (const float*)d_in[0];
    const float* conv_w = (const float*)d_in[1];
    // d_in[2] = conv_b: cancels exactly under mean-centering; unused.
    const float* proj_w = (const float*)d_in[3];
    const float* proj_b = (const float*)d_in[4];
    const float* head_w = (const float*)d_in[5];
    const float* head_b = (const float*)d_in[6];

    int B = in_sizes[0] / (CCH * TT);
    if (B > NB) B = NB;

    fused_kernel<<<B, 256>>>(x, conv_w, proj_w, proj_b, head_w, head_b,
                             (float*)d_out);
}